// round 11
// baseline (speedup 1.0000x reference)
#include <cuda_runtime.h>
#include <cuda_bf16.h>
#include <cstdint>

#define DIM   2048
#define BATCH 64
#define NTOK  (BATCH * DIM)

// q/k/v partials: [mat(q,k,v)][ksplit(2)][b][n]
__device__ float g_qkv2[6 * NTOK];

// ---------------------------------------------------------------------------
// Packed f32x2 helpers (Blackwell sm_103a)
// ---------------------------------------------------------------------------
__device__ __forceinline__ uint64_t mul2(uint64_t a, uint64_t b) {
    uint64_t d; asm("mul.rn.f32x2 %0,%1,%2;" : "=l"(d) : "l"(a), "l"(b)); return d;
}
__device__ __forceinline__ uint64_t add2(uint64_t a, uint64_t b) {
    uint64_t d; asm("add.rn.f32x2 %0,%1,%2;" : "=l"(d) : "l"(a), "l"(b)); return d;
}
__device__ __forceinline__ uint64_t fma2(uint64_t a, uint64_t b, uint64_t c) {
    uint64_t d; asm("fma.rn.f32x2 %0,%1,%2,%3;" : "=l"(d) : "l"(a), "l"(b), "l"(c)); return d;
}
__device__ __forceinline__ uint64_t pk2(float lo, float hi) {
    uint64_t d; asm("mov.b64 %0,{%1,%2};" : "=l"(d) : "f"(lo), "f"(hi)); return d;
}
__device__ __forceinline__ void up2(uint64_t v, float& lo, float& hi) {
    asm("mov.b64 {%0,%1},%2;" : "=f"(lo), "=f"(hi) : "l"(v));
}
__device__ __forceinline__ float ex2f(float x) {
    float r; asm("ex2.approx.ftz.f32 %0,%1;" : "=f"(r) : "f"(x)); return r;
}

// ---------------------------------------------------------------------------
// Kernel 1: q/k/v = x @ W^T   fp32, f32x2 FMA, cp.async double-buffer, K-split 2
// Block: 256 thr, tile 64b x 32n x 1024k. Grid: (64 n-tiles, 3 mats * 2 ksplit).
// ---------------------------------------------------------------------------
#define KT     32
#define KTP    36          // row stride (floats); 36 % 32 == 4 -> conflict-free 16B LDS
#define KHALF  1024
#define NCHUNK (KHALF / KT)

__global__ __launch_bounds__(256, 2) void qkv_gemm_kernel(
    const float* __restrict__ x,
    const float* __restrict__ Wq,
    const float* __restrict__ Wk,
    const float* __restrict__ Wv)
{
    const int mat = blockIdx.y >> 1;
    const int ks  = blockIdx.y & 1;
    const float* __restrict__ W = (mat == 0) ? Wq : ((mat == 1) ? Wk : Wv);
    float* dst = g_qkv2 + (size_t)(mat * 2 + ks) * NTOK;

    __shared__ __align__(16) float sX[2][64 * KTP];
    __shared__ __align__(16) float sW[2][32 * KTP];

    const int tid = threadIdx.x;
    const int n0  = blockIdx.x * 32;
    const int kbase = ks * KHALF;

    const int ng = tid & 15;
    const int bb = (tid >> 4) * 4;

    // loader indices (float4 granularity, coalesced)
    const int xr0 = tid >> 3;            // 0..31   (i=0)
    const int xr1 = (tid + 256) >> 3;    // 32..63  (i=1)
    const int xc4 = (tid & 7) * 4;       // float col 0,4,...,28
    const int wr  = tid >> 3;            // 0..31
    const int wc4 = (tid & 7) * 4;

    uint64_t acc[4][2];
#pragma unroll
    for (int i = 0; i < 4; i++) { acc[i][0] = 0ull; acc[i][1] = 0ull; }

#define LD_CHUNK(buf, c)                                                        \
    do {                                                                        \
        const int k0_ = kbase + (c) * KT;                                       \
        uint32_t d0 = (uint32_t)__cvta_generic_to_shared(&sX[buf][xr0 * KTP + xc4]); \
        const float* s0 = &x[(size_t)xr0 * DIM + k0_ + xc4];                    \
        asm volatile("cp.async.cg.shared.global [%0], [%1], 16;" :: "r"(d0), "l"(s0)); \
        uint32_t d1 = (uint32_t)__cvta_generic_to_shared(&sX[buf][xr1 * KTP + xc4]); \
        const float* s1 = &x[(size_t)xr1 * DIM + k0_ + xc4];                    \
        asm volatile("cp.async.cg.shared.global [%0], [%1], 16;" :: "r"(d1), "l"(s1)); \
        uint32_t d2 = (uint32_t)__cvta_generic_to_shared(&sW[buf][wr * KTP + wc4]);  \
        const float* s2 = &W[(size_t)(n0 + wr) * DIM + k0_ + wc4];              \
        asm volatile("cp.async.cg.shared.global [%0], [%1], 16;" :: "r"(d2), "l"(s2)); \
        asm volatile("cp.async.commit_group;");                                 \
    } while (0)

    LD_CHUNK(0, 0);

    for (int c = 0; c < NCHUNK; ++c) {
        if (c + 1 < NCHUNK) {
            LD_CHUNK((c + 1) & 1, c + 1);
            asm volatile("cp.async.wait_group 1;");
        } else {
            asm volatile("cp.async.wait_group 0;");
        }
        __syncthreads();

        const float* bX = sX[c & 1];
        const float* bW = sW[c & 1];

#pragma unroll
        for (int kk = 0; kk < KT; kk += 4) {
            ulonglong2 xv[4];
#pragma unroll
            for (int bi = 0; bi < 4; bi++)
                xv[bi] = *(const ulonglong2*)&bX[(bb + bi) * KTP + kk];
            ulonglong2 wv0 = *(const ulonglong2*)&bW[ng * KTP + kk];
            ulonglong2 wv1 = *(const ulonglong2*)&bW[(ng + 16) * KTP + kk];
#pragma unroll
            for (int bi = 0; bi < 4; bi++) {
                acc[bi][0] = fma2(xv[bi].x, wv0.x, acc[bi][0]);
                acc[bi][0] = fma2(xv[bi].y, wv0.y, acc[bi][0]);
                acc[bi][1] = fma2(xv[bi].x, wv1.x, acc[bi][1]);
                acc[bi][1] = fma2(xv[bi].y, wv1.y, acc[bi][1]);
            }
        }
        __syncthreads();   // protect buf (c&1) before it is refilled at iter c+1
    }

#pragma unroll
    for (int bi = 0; bi < 4; bi++) {
#pragma unroll
        for (int nj = 0; nj < 2; nj++) {
            float lo, hi; up2(acc[bi][nj], lo, hi);
            dst[(size_t)(bb + bi) * DIM + n0 + ng + nj * 16] = lo + hi;
        }
    }
#undef LD_CHUNK
}

// ---------------------------------------------------------------------------
// Kernel 2: attention, MUFU + polynomial-exp2 hybrid (5 MUFU pairs : 3 poly pairs
// per 16 j) to push exp throughput past the MUFU-only ceiling.
// ---------------------------------------------------------------------------
#define MAGIC 12582912.0f  // 2^23 + 2^22 : round-to-nearest-int via FADD

__global__ __launch_bounds__(128) void attn_kernel(float* __restrict__ out)
{
    __shared__ __align__(16) float sk[DIM];
    __shared__ __align__(16) float sv[DIM];

    const int b   = blockIdx.y;
    const int tid = threadIdx.x;

    const float* __restrict__ q0 = g_qkv2 + 0 * (size_t)NTOK + (size_t)b * DIM;
    const float* __restrict__ q1 = g_qkv2 + 1 * (size_t)NTOK + (size_t)b * DIM;
    const float* __restrict__ k0 = g_qkv2 + 2 * (size_t)NTOK + (size_t)b * DIM;
    const float* __restrict__ k1 = g_qkv2 + 3 * (size_t)NTOK + (size_t)b * DIM;
    const float* __restrict__ v0 = g_qkv2 + 4 * (size_t)NTOK + (size_t)b * DIM;
    const float* __restrict__ v1 = g_qkv2 + 5 * (size_t)NTOK + (size_t)b * DIM;

    // Fill smem, summing the two K-split partials.
#pragma unroll
    for (int t = tid; t < DIM / 4; t += 128) {
        float4 a = ((const float4*)k0)[t], c = ((const float4*)k1)[t];
        float4 r; r.x = a.x + c.x; r.y = a.y + c.y; r.z = a.z + c.z; r.w = a.w + c.w;
        ((float4*)sk)[t] = r;
        float4 e = ((const float4*)v0)[t], f = ((const float4*)v1)[t];
        float4 s; s.x = e.x + f.x; s.y = e.y + f.y; s.z = e.z + f.z; s.w = e.w + f.w;
        ((float4*)sv)[t] = s;
    }
    __syncthreads();

    const int i = blockIdx.x * 128 + tid;
    const float tq = (q0[i] + q1[i]) * 1.4426950408889634f;  // q_i * log2(e)
    const uint64_t tt = pk2(tq, tq);

    const uint64_t MM2 = pk2(MAGIC, MAGIC);
    const uint64_t NM2 = pk2(-MAGIC, -MAGIC);
    const uint64_t N12 = pk2(-1.0f, -1.0f);
    const uint64_t C4  = pk2(0.0096181291f, 0.0096181291f);
    const uint64_t C3  = pk2(0.0555041087f, 0.0555041087f);
    const uint64_t C2  = pk2(0.2402265070f, 0.2402265070f);
    const uint64_t C1  = pk2(0.6931471806f, 0.6931471806f);
    const uint64_t C0  = pk2(1.0f, 1.0f);

    uint64_t nA = 0, nB = 0, dA = 0, dB = 0;

    const ulonglong2* __restrict__ k2 = (const ulonglong2*)sk;  // 2 f32x2-pairs each
    const ulonglong2* __restrict__ v2 = (const ulonglong2*)sv;

#define MUFU_PAIR(KP, VP, NACC, DACC)                         \
    do {                                                      \
        uint64_t r_ = mul2(tt, (KP));                         \
        float rl_, rh_; up2(r_, rl_, rh_);                    \
        uint64_t e_ = pk2(ex2f(rl_), ex2f(rh_));              \
        NACC = fma2(e_, (VP), NACC);                          \
        DACC = add2(DACC, e_);                                \
    } while (0)

#define POLY_PAIR(KP, VP, NACC, DACC)                         \
    do {                                                      \
        uint64_t r_ = mul2(tt, (KP));                         \
        uint64_t y_ = add2(r_, MM2);                          \
        uint64_t z_ = add2(y_, NM2);          /* round(r) */  \
        uint64_t f_ = fma2(z_, N12, r_);      /* r-round(r)*/ \
        uint64_t p_ = fma2(C4, f_, C3);                       \
        p_ = fma2(p_, f_, C2);                                \
        p_ = fma2(p_, f_, C1);                                \
        p_ = fma2(p_, f_, C0);                                \
        uint32_t y0_, y1_, p0_, p1_;                          \
        asm("mov.b64 {%0,%1},%2;" : "=r"(y0_), "=r"(y1_) : "l"(y_)); \
        asm("mov.b64 {%0,%1},%2;" : "=r"(p0_), "=r"(p1_) : "l"(p_)); \
        uint32_t e0_ = p0_ + (y0_ << 23);                     \
        uint32_t e1_ = p1_ + (y1_ << 23);                     \
        uint64_t e_;                                          \
        asm("mov.b64 %0,{%1,%2};" : "=l"(e_) : "r"(e0_), "r"(e1_)); \
        NACC = fma2(e_, (VP), NACC);                          \
        DACC = add2(DACC, e_);                                \
    } while (0)

#pragma unroll 2
    for (int it = 0; it < DIM / 16; ++it) {
        const int base = it * 4;  // ulonglong2 index (4 per iter = 16 floats)
        ulonglong2 ka = k2[base + 0], kb = k2[base + 1];
        ulonglong2 kc = k2[base + 2], kd = k2[base + 3];
        ulonglong2 va = v2[base + 0], vb = v2[base + 1];
        ulonglong2 vc = v2[base + 2], vd = v2[base + 3];

        MUFU_PAIR(ka.x, va.x, nA, dA);
        MUFU_PAIR(ka.y, va.y, nB, dB);
        MUFU_PAIR(kb.x, vb.x, nA, dA);
        MUFU_PAIR(kb.y, vb.y, nB, dB);
        MUFU_PAIR(kc.x, vc.x, nA, dA);
        POLY_PAIR(kc.y, vc.y, nB, dB);
        POLY_PAIR(kd.x, vd.x, nA, dA);
        POLY_PAIR(kd.y, vd.y, nB, dB);
    }

    float n0f, n1f, n2f, n3f, d0f, d1f, d2f, d3f;
    up2(nA, n0f, n1f); up2(nB, n2f, n3f);
    up2(dA, d0f, d1f); up2(dB, d2f, d3f);
    const float num = (n0f + n1f) + (n2f + n3f);
    const float den = (d0f + d1f) + (d2f + d3f);
    out[(size_t)b * DIM + i] = num / den;

#undef MUFU_PAIR
#undef POLY_PAIR
}

// ---------------------------------------------------------------------------
extern "C" void kernel_launch(void* const* d_in, const int* in_sizes, int n_in,
                              void* d_out, int out_size)
{
    const float* x  = (const float*)d_in[0];
    const float* Wq = (const float*)d_in[1];
    const float* Wk = (const float*)d_in[2];
    const float* Wv = (const float*)d_in[3];
    float* out = (float*)d_out;

    dim3 g1(DIM / 32, 6);   // 64 n-tiles x (3 mats * 2 k-splits) = 384 blocks
    qkv_gemm_kernel<<<g1, 256>>>(x, Wq, Wk, Wv);

    dim3 g2(DIM / 128, BATCH);
    attn_kernel<<<g2, 128>>>(out);
}

// round 12
// speedup vs baseline: 1.0137x; 1.0137x over previous
#include <cuda_runtime.h>
#include <cuda_bf16.h>
#include <cstdint>

#define DIM   2048
#define BATCH 64
#define NTOK  (BATCH * DIM)

// q/k/v partials: [mat(q,k,v)][ksplit(2)][b][n]
__device__ float g_qkv2[6 * NTOK];

// ---------------------------------------------------------------------------
// Packed f32x2 helpers (Blackwell sm_103a)
// ---------------------------------------------------------------------------
__device__ __forceinline__ uint64_t mul2(uint64_t a, uint64_t b) {
    uint64_t d; asm("mul.rn.f32x2 %0,%1,%2;" : "=l"(d) : "l"(a), "l"(b)); return d;
}
__device__ __forceinline__ uint64_t add2(uint64_t a, uint64_t b) {
    uint64_t d; asm("add.rn.f32x2 %0,%1,%2;" : "=l"(d) : "l"(a), "l"(b)); return d;
}
__device__ __forceinline__ uint64_t fma2(uint64_t a, uint64_t b, uint64_t c) {
    uint64_t d; asm("fma.rn.f32x2 %0,%1,%2,%3;" : "=l"(d) : "l"(a), "l"(b), "l"(c)); return d;
}
__device__ __forceinline__ uint64_t pk2(float lo, float hi) {
    uint64_t d; asm("mov.b64 %0,{%1,%2};" : "=l"(d) : "f"(lo), "f"(hi)); return d;
}
__device__ __forceinline__ void up2(uint64_t v, float& lo, float& hi) {
    asm("mov.b64 {%0,%1},%2;" : "=f"(lo), "=f"(hi) : "l"(v));
}
__device__ __forceinline__ float ex2f(float x) {
    float r; asm("ex2.approx.ftz.f32 %0,%1;" : "=f"(r) : "f"(x)); return r;
}

// ---------------------------------------------------------------------------
// Kernel 1: q/k/v = x @ W^T   fp32, f32x2 FMA, cp.async double-buffer, K-split 2
// Block: 256 thr, tile 64b x 32n x 1024k. Grid: (64 n-tiles, 3 mats * 2 ksplit).
// ---------------------------------------------------------------------------
#define KT     32
#define KTP    36          // row stride (floats); 36 % 32 == 4 -> conflict-free 16B LDS
#define KHALF  1024
#define NCHUNK (KHALF / KT)

__global__ __launch_bounds__(256, 2) void qkv_gemm_kernel(
    const float* __restrict__ x,
    const float* __restrict__ Wq,
    const float* __restrict__ Wk,
    const float* __restrict__ Wv)
{
    const int mat = blockIdx.y >> 1;
    const int ks  = blockIdx.y & 1;
    const float* __restrict__ W = (mat == 0) ? Wq : ((mat == 1) ? Wk : Wv);
    float* dst = g_qkv2 + (size_t)(mat * 2 + ks) * NTOK;

    __shared__ __align__(16) float sX[2][64 * KTP];
    __shared__ __align__(16) float sW[2][32 * KTP];

    const int tid = threadIdx.x;
    const int n0  = blockIdx.x * 32;
    const int kbase = ks * KHALF;

    const int ng = tid & 15;
    const int bb = (tid >> 4) * 4;

    // loader indices (float4 granularity, coalesced)
    const int xr0 = tid >> 3;            // 0..31   (i=0)
    const int xr1 = (tid + 256) >> 3;    // 32..63  (i=1)
    const int xc4 = (tid & 7) * 4;       // float col 0,4,...,28
    const int wr  = tid >> 3;            // 0..31
    const int wc4 = (tid & 7) * 4;

    uint64_t acc[4][2];
#pragma unroll
    for (int i = 0; i < 4; i++) { acc[i][0] = 0ull; acc[i][1] = 0ull; }

#define LD_CHUNK(buf, c)                                                        \
    do {                                                                        \
        const int k0_ = kbase + (c) * KT;                                       \
        uint32_t d0 = (uint32_t)__cvta_generic_to_shared(&sX[buf][xr0 * KTP + xc4]); \
        const float* s0 = &x[(size_t)xr0 * DIM + k0_ + xc4];                    \
        asm volatile("cp.async.cg.shared.global [%0], [%1], 16;" :: "r"(d0), "l"(s0)); \
        uint32_t d1 = (uint32_t)__cvta_generic_to_shared(&sX[buf][xr1 * KTP + xc4]); \
        const float* s1 = &x[(size_t)xr1 * DIM + k0_ + xc4];                    \
        asm volatile("cp.async.cg.shared.global [%0], [%1], 16;" :: "r"(d1), "l"(s1)); \
        uint32_t d2 = (uint32_t)__cvta_generic_to_shared(&sW[buf][wr * KTP + wc4]);  \
        const float* s2 = &W[(size_t)(n0 + wr) * DIM + k0_ + wc4];              \
        asm volatile("cp.async.cg.shared.global [%0], [%1], 16;" :: "r"(d2), "l"(s2)); \
        asm volatile("cp.async.commit_group;");                                 \
    } while (0)

    LD_CHUNK(0, 0);

    for (int c = 0; c < NCHUNK; ++c) {
        if (c + 1 < NCHUNK) {
            LD_CHUNK((c + 1) & 1, c + 1);
            asm volatile("cp.async.wait_group 1;");
        } else {
            asm volatile("cp.async.wait_group 0;");
        }
        __syncthreads();

        const float* bX = sX[c & 1];
        const float* bW = sW[c & 1];

#pragma unroll
        for (int kk = 0; kk < KT; kk += 4) {
            ulonglong2 xv[4];
#pragma unroll
            for (int bi = 0; bi < 4; bi++)
                xv[bi] = *(const ulonglong2*)&bX[(bb + bi) * KTP + kk];
            ulonglong2 wv0 = *(const ulonglong2*)&bW[ng * KTP + kk];
            ulonglong2 wv1 = *(const ulonglong2*)&bW[(ng + 16) * KTP + kk];
#pragma unroll
            for (int bi = 0; bi < 4; bi++) {
                acc[bi][0] = fma2(xv[bi].x, wv0.x, acc[bi][0]);
                acc[bi][0] = fma2(xv[bi].y, wv0.y, acc[bi][0]);
                acc[bi][1] = fma2(xv[bi].x, wv1.x, acc[bi][1]);
                acc[bi][1] = fma2(xv[bi].y, wv1.y, acc[bi][1]);
            }
        }
        __syncthreads();   // protect buf (c&1) before it is refilled at iter c+1
    }

#pragma unroll
    for (int bi = 0; bi < 4; bi++) {
#pragma unroll
        for (int nj = 0; nj < 2; nj++) {
            float lo, hi; up2(acc[bi][nj], lo, hi);
            dst[(size_t)(bb + bi) * DIM + n0 + ng + nj * 16] = lo + hi;
        }
    }
#undef LD_CHUNK
}

// ---------------------------------------------------------------------------
// Kernel 2: attention, MUFU + polynomial-exp2 hybrid (5 MUFU pairs : 3 poly pairs
// per 16 j) to push exp throughput past the MUFU-only ceiling.
// ---------------------------------------------------------------------------
#define MAGIC 12582912.0f  // 2^23 + 2^22 : round-to-nearest-int via FADD

__global__ __launch_bounds__(128) void attn_kernel(float* __restrict__ out)
{
    __shared__ __align__(16) float sk[DIM];
    __shared__ __align__(16) float sv[DIM];

    const int b   = blockIdx.y;
    const int tid = threadIdx.x;

    const float* __restrict__ q0 = g_qkv2 + 0 * (size_t)NTOK + (size_t)b * DIM;
    const float* __restrict__ q1 = g_qkv2 + 1 * (size_t)NTOK + (size_t)b * DIM;
    const float* __restrict__ k0 = g_qkv2 + 2 * (size_t)NTOK + (size_t)b * DIM;
    const float* __restrict__ k1 = g_qkv2 + 3 * (size_t)NTOK + (size_t)b * DIM;
    const float* __restrict__ v0 = g_qkv2 + 4 * (size_t)NTOK + (size_t)b * DIM;
    const float* __restrict__ v1 = g_qkv2 + 5 * (size_t)NTOK + (size_t)b * DIM;

    // Fill smem, summing the two K-split partials.
#pragma unroll
    for (int t = tid; t < DIM / 4; t += 128) {
        float4 a = ((const float4*)k0)[t], c = ((const float4*)k1)[t];
        float4 r; r.x = a.x + c.x; r.y = a.y + c.y; r.z = a.z + c.z; r.w = a.w + c.w;
        ((float4*)sk)[t] = r;
        float4 e = ((const float4*)v0)[t], f = ((const float4*)v1)[t];
        float4 s; s.x = e.x + f.x; s.y = e.y + f.y; s.z = e.z + f.z; s.w = e.w + f.w;
        ((float4*)sv)[t] = s;
    }
    __syncthreads();

    const int i = blockIdx.x * 128 + tid;
    const float tq = (q0[i] + q1[i]) * 1.4426950408889634f;  // q_i * log2(e)
    const uint64_t tt = pk2(tq, tq);

    const uint64_t MM2 = pk2(MAGIC, MAGIC);
    const uint64_t NM2 = pk2(-MAGIC, -MAGIC);
    const uint64_t N12 = pk2(-1.0f, -1.0f);
    const uint64_t C4  = pk2(0.0096181291f, 0.0096181291f);
    const uint64_t C3  = pk2(0.0555041087f, 0.0555041087f);
    const uint64_t C2  = pk2(0.2402265070f, 0.2402265070f);
    const uint64_t C1  = pk2(0.6931471806f, 0.6931471806f);
    const uint64_t C0  = pk2(1.0f, 1.0f);

    uint64_t nA = 0, nB = 0, dA = 0, dB = 0;

    const ulonglong2* __restrict__ k2 = (const ulonglong2*)sk;  // 2 f32x2-pairs each
    const ulonglong2* __restrict__ v2 = (const ulonglong2*)sv;

#define MUFU_PAIR(KP, VP, NACC, DACC)                         \
    do {                                                      \
        uint64_t r_ = mul2(tt, (KP));                         \
        float rl_, rh_; up2(r_, rl_, rh_);                    \
        uint64_t e_ = pk2(ex2f(rl_), ex2f(rh_));              \
        NACC = fma2(e_, (VP), NACC);                          \
        DACC = add2(DACC, e_);                                \
    } while (0)

#define POLY_PAIR(KP, VP, NACC, DACC)                         \
    do {                                                      \
        uint64_t r_ = mul2(tt, (KP));                         \
        uint64_t y_ = add2(r_, MM2);                          \
        uint64_t z_ = add2(y_, NM2);          /* round(r) */  \
        uint64_t f_ = fma2(z_, N12, r_);      /* r-round(r)*/ \
        uint64_t p_ = fma2(C4, f_, C3);                       \
        p_ = fma2(p_, f_, C2);                                \
        p_ = fma2(p_, f_, C1);                                \
        p_ = fma2(p_, f_, C0);                                \
        uint32_t y0_, y1_, p0_, p1_;                          \
        asm("mov.b64 {%0,%1},%2;" : "=r"(y0_), "=r"(y1_) : "l"(y_)); \
        asm("mov.b64 {%0,%1},%2;" : "=r"(p0_), "=r"(p1_) : "l"(p_)); \
        uint32_t e0_ = p0_ + (y0_ << 23);                     \
        uint32_t e1_ = p1_ + (y1_ << 23);                     \
        uint64_t e_;                                          \
        asm("mov.b64 %0,{%1,%2};" : "=l"(e_) : "r"(e0_), "r"(e1_)); \
        NACC = fma2(e_, (VP), NACC);                          \
        DACC = add2(DACC, e_);                                \
    } while (0)

#pragma unroll 2
    for (int it = 0; it < DIM / 16; ++it) {
        const int base = it * 4;  // ulonglong2 index (4 per iter = 16 floats)
        ulonglong2 ka = k2[base + 0], kb = k2[base + 1];
        ulonglong2 kc = k2[base + 2], kd = k2[base + 3];
        ulonglong2 va = v2[base + 0], vb = v2[base + 1];
        ulonglong2 vc = v2[base + 2], vd = v2[base + 3];

        MUFU_PAIR(ka.x, va.x, nA, dA);
        MUFU_PAIR(ka.y, va.y, nB, dB);
        MUFU_PAIR(kb.x, vb.x, nA, dA);
        MUFU_PAIR(kb.y, vb.y, nB, dB);
        MUFU_PAIR(kc.x, vc.x, nA, dA);
        POLY_PAIR(kc.y, vc.y, nB, dB);
        POLY_PAIR(kd.x, vd.x, nA, dA);
        POLY_PAIR(kd.y, vd.y, nB, dB);
    }

    float n0f, n1f, n2f, n3f, d0f, d1f, d2f, d3f;
    up2(nA, n0f, n1f); up2(nB, n2f, n3f);
    up2(dA, d0f, d1f); up2(dB, d2f, d3f);
    const float num = (n0f + n1f) + (n2f + n3f);
    const float den = (d0f + d1f) + (d2f + d3f);
    out[(size_t)b * DIM + i] = num / den;

#undef MUFU_PAIR
#undef POLY_PAIR
}

// ---------------------------------------------------------------------------
extern "C" void kernel_launch(void* const* d_in, const int* in_sizes, int n_in,
                              void* d_out, int out_size)
{
    const float* x  = (const float*)d_in[0];
    const float* Wq = (const float*)d_in[1];
    const float* Wk = (const float*)d_in[2];
    const float* Wv = (const float*)d_in[3];
    float* out = (float*)d_out;

    dim3 g1(DIM / 32, 6);   // 64 n-tiles x (3 mats * 2 k-splits) = 384 blocks
    qkv_gemm_kernel<<<g1, 256>>>(x, Wq, Wk, Wv);

    dim3 g2(DIM / 128, BATCH);
    attn_kernel<<<g2, 128>>>(out);
}